// round 2
// baseline (speedup 1.0000x reference)
#include <cuda_runtime.h>

#define N_NODES 100000
#define N_EDGES 1600000
#define H0 256
#define H1 1024
#define IN_DIM 64

// Scratch (no allocations allowed in kernel_launch)
__device__ float g_h0[H0];
__device__ float g_h1[H1];
__device__ float g_x[N_NODES];     // relu(FC2 output)
__device__ float g_deg[N_NODES];   // degree (with self loop)
__device__ float g_dinv[N_NODES];  // deg^-1/2

__device__ __forceinline__ float warp_sum(float s) {
#pragma unroll
    for (int o = 16; o; o >>= 1) s += __shfl_xor_sync(0xffffffffu, s, o);
    return s;
}

// ---------------------------------------------------------------------------
// FC0: [64] -> [256], one block of 256 threads, one row per thread.
// ---------------------------------------------------------------------------
__global__ void fc0_kernel(const float* __restrict__ emb,
                           const float* __restrict__ W0,
                           const float* __restrict__ b0) {
    __shared__ float se[IN_DIM];
    int t = threadIdx.x;
    if (t < IN_DIM) se[t] = emb[t];
    __syncthreads();

    const float4* w = reinterpret_cast<const float4*>(W0 + (size_t)t * IN_DIM);
    const float4* h = reinterpret_cast<const float4*>(se);
    float s = 0.f;
#pragma unroll
    for (int i = 0; i < IN_DIM / 4; i++) {
        float4 wv = w[i];
        float4 hv = h[i];
        s += wv.x * hv.x + wv.y * hv.y + wv.z * hv.z + wv.w * hv.w;
    }
    s += b0[t];
    g_h0[t] = fmaxf(s, 0.f);
}

// ---------------------------------------------------------------------------
// FC1: [256] -> [1024], warp-per-row. 128 blocks x 256 threads = 1024 warps.
// ---------------------------------------------------------------------------
__global__ void fc1_kernel(const float* __restrict__ W1,
                           const float* __restrict__ b1) {
    __shared__ float sh[H0];
    int t = threadIdx.x;
    sh[t] = g_h0[t];  // blockDim == 256 == H0
    __syncthreads();

    int row  = (blockIdx.x * blockDim.x + t) >> 5;
    int lane = t & 31;
    if (row >= H1) return;

    const float4* w = reinterpret_cast<const float4*>(W1 + (size_t)row * H0);
    const float4* h = reinterpret_cast<const float4*>(sh);
    float s = 0.f;
#pragma unroll
    for (int i = lane; i < H0 / 4; i += 32) {
        float4 wv = w[i];
        float4 hv = h[i];
        s += wv.x * hv.x + wv.y * hv.y + wv.z * hv.z + wv.w * hv.w;
    }
    s = warp_sum(s);
    if (lane == 0) g_h1[row] = fmaxf(s + b1[row], 0.f);
}

// ---------------------------------------------------------------------------
// FC2 (dominant): [1024] -> [100000], warp-per-row GEMV + ReLU.
// 409.6 MB of W2 streamed once; the HBM roofline of the whole problem.
// ---------------------------------------------------------------------------
__global__ void fc2_kernel(const float* __restrict__ W2,
                           const float* __restrict__ b2) {
    __shared__ float sh[H1];
    int t = threadIdx.x;
#pragma unroll
    for (int i = t; i < H1; i += 256) sh[i] = g_h1[i];
    __syncthreads();

    int row  = blockIdx.x * 8 + (t >> 5);
    int lane = t & 31;
    if (row >= N_NODES) return;

    const float4* w = reinterpret_cast<const float4*>(W2 + (size_t)row * H1);
    const float4* h = reinterpret_cast<const float4*>(sh);
    float s = 0.f;
#pragma unroll
    for (int i = lane; i < H1 / 4; i += 32) {  // 8 float4 per lane
        float4 wv = __ldg(&w[i]);
        float4 hv = h[i];
        s += wv.x * hv.x + wv.y * hv.y + wv.z * hv.z + wv.w * hv.w;
    }
    s = warp_sum(s);
    if (lane == 0) g_x[row] = fmaxf(s + b2[row], 0.f);
}

// ---------------------------------------------------------------------------
// GCN: degree init (self loop contributes 1)
// ---------------------------------------------------------------------------
__global__ void deg_init_kernel() {
    int i = blockIdx.x * blockDim.x + threadIdx.x;
    if (i < N_NODES) g_deg[i] = 1.0f;
}

// degree count over dst (edge_index is int32 — JAX x64 disabled)
__global__ void deg_count_kernel(const int* __restrict__ dst) {
    int e = blockIdx.x * blockDim.x + threadIdx.x;
    if (e < N_EDGES) atomicAdd(&g_deg[dst[e]], 1.0f);
}

// self-loop message + bias + dinv precompute
// out[i] = gcn_b + gcn_w * x[i] * dinv[i]^2 ; dinv[i] = rsqrt(deg[i])
__global__ void self_msg_kernel(float* __restrict__ out,
                                const float* __restrict__ gw,
                                const float* __restrict__ gb) {
    int i = blockIdx.x * blockDim.x + threadIdx.x;
    if (i >= N_NODES) return;
    float d  = g_deg[i];
    float di = rsqrtf(d);
    g_dinv[i] = di;
    out[i] = gb[0] + gw[0] * g_x[i] * di * di;
}

// edge scatter: out[dst] += gcn_w * x[src] * dinv[src] * dinv[dst]
__global__ void scatter_kernel(const int* __restrict__ src,
                               const int* __restrict__ dst,
                               float* __restrict__ out,
                               const float* __restrict__ gw) {
    int e = blockIdx.x * blockDim.x + threadIdx.x;
    if (e >= N_EDGES) return;
    int s = src[e];
    int d = dst[e];
    float v = gw[0] * g_x[s] * g_dinv[s] * g_dinv[d];
    atomicAdd(&out[d], v);
}

// ---------------------------------------------------------------------------
extern "C" void kernel_launch(void* const* d_in, const int* in_sizes, int n_in,
                              void* d_out, int out_size) {
    const float* emb = (const float*)d_in[0];
    const int*   ei  = (const int*)d_in[1];  // [2, E] int32 (JAX x64 off)
    const float* W0  = (const float*)d_in[2];
    const float* b0  = (const float*)d_in[3];
    const float* W1  = (const float*)d_in[4];
    const float* b1  = (const float*)d_in[5];
    const float* W2  = (const float*)d_in[6];
    const float* b2  = (const float*)d_in[7];
    const float* gw  = (const float*)d_in[8];
    const float* gb  = (const float*)d_in[9];
    float*       out = (float*)d_out;

    const int* src = ei;            // row 0
    const int* dst = ei + N_EDGES;  // row 1

    fc0_kernel<<<1, 256>>>(emb, W0, b0);
    fc1_kernel<<<H1 / 8, 256>>>(W1, b1);
    fc2_kernel<<<(N_NODES + 7) / 8, 256>>>(W2, b2);

    deg_init_kernel<<<(N_NODES + 255) / 256, 256>>>();
    deg_count_kernel<<<(N_EDGES + 255) / 256, 256>>>(dst);
    self_msg_kernel<<<(N_NODES + 255) / 256, 256>>>(out, gw, gb);
    scatter_kernel<<<(N_EDGES + 255) / 256, 256>>>(src, dst, out, gw);
}

// round 3
// speedup vs baseline: 1.1302x; 1.1302x over previous
#include <cuda_runtime.h>

#define N_NODES 100000
#define N_EDGES 1600000
#define H0 256
#define H1 1024
#define IN_DIM 64

// Scratch (no allocations allowed)
__device__ float g_h0[H0];
__device__ float g_h1[H1];
__device__ float g_deg[N_NODES];   // degree (incl. self loop)
__device__ float g_dinv[N_NODES];  // deg^-1/2
__device__ float g_xd[N_NODES];    // gcn_w * x[i] * dinv[i]

__device__ __forceinline__ float warp_sum(float s) {
#pragma unroll
    for (int o = 16; o; o >>= 1) s += __shfl_xor_sync(0xffffffffu, s, o);
    return s;
}

// ---------------------------------------------------------------------------
// L1: block 0 computes FC0 (64 -> 256); ALL blocks init deg slice to 1.0
// grid = 391 blocks x 256 threads
// ---------------------------------------------------------------------------
__global__ void k1_fc0_deginit(const float* __restrict__ emb,
                               const float* __restrict__ W0,
                               const float* __restrict__ b0) {
    int t = threadIdx.x;
    int gi = blockIdx.x * blockDim.x + t;
    if (gi < N_NODES) g_deg[gi] = 1.0f;

    if (blockIdx.x == 0) {
        __shared__ float se[IN_DIM];
        if (t < IN_DIM) se[t] = emb[t];
        __syncthreads();

        const float4* w = reinterpret_cast<const float4*>(W0 + (size_t)t * IN_DIM);
        const float4* h = reinterpret_cast<const float4*>(se);
        float s = 0.f;
#pragma unroll
        for (int i = 0; i < IN_DIM / 4; i++) {
            float4 wv = w[i];
            float4 hv = h[i];
            s += wv.x * hv.x + wv.y * hv.y + wv.z * hv.z + wv.w * hv.w;
        }
        g_h0[t] = fmaxf(s + b0[t], 0.f);
    }
}

// ---------------------------------------------------------------------------
// L2: blocks 0..127 compute FC1 (256 -> 1024, warp-per-row);
//     ALL blocks count degrees over a 1024-edge slice (int4 loads).
// grid = 1563 blocks x 256 threads
// ---------------------------------------------------------------------------
__global__ void k2_fc1_degcount(const float* __restrict__ W1,
                                const float* __restrict__ b1,
                                const int*   __restrict__ dst) {
    int t = threadIdx.x;

    // degree slice: 4 edges per thread
    int e4 = blockIdx.x * blockDim.x + t;  // index into int4 view
    if (e4 * 4 < N_EDGES) {
        int4 d4 = reinterpret_cast<const int4*>(dst)[e4];
        atomicAdd(&g_deg[d4.x], 1.0f);
        atomicAdd(&g_deg[d4.y], 1.0f);
        atomicAdd(&g_deg[d4.z], 1.0f);
        atomicAdd(&g_deg[d4.w], 1.0f);
    }

    if (blockIdx.x < H1 / 8) {
        __shared__ float sh[H0];
        sh[t] = g_h0[t];  // blockDim == 256 == H0
        __syncthreads();

        int row  = blockIdx.x * 8 + (t >> 5);
        int lane = t & 31;
        const float4* w = reinterpret_cast<const float4*>(W1 + (size_t)row * H0);
        const float4* h = reinterpret_cast<const float4*>(sh);
        float s = 0.f;
#pragma unroll
        for (int i = lane; i < H0 / 4; i += 32) {
            float4 wv = w[i];
            float4 hv = h[i];
            s += wv.x * hv.x + wv.y * hv.y + wv.z * hv.z + wv.w * hv.w;
        }
        s = warp_sum(s);
        if (lane == 0) g_h1[row] = fmaxf(s + b1[row], 0.f);
    }
}

// ---------------------------------------------------------------------------
// L3 (dominant): FC2 GEMV [1024]->[100000] + ReLU + fused GCN node epilogue.
//   x        = relu(W2[row] . h1 + b2[row])
//   dinv     = rsqrt(deg[row])
//   g_xd     = gcn_w * x * dinv
//   out[row] = gcn_b + g_xd * dinv          (bias + self-loop message)
// grid = 12500 blocks x 256 threads, warp-per-row, float4 streaming loads.
// ---------------------------------------------------------------------------
__global__ void k3_fc2_selfmsg(const float* __restrict__ W2,
                               const float* __restrict__ b2,
                               const float* __restrict__ gw,
                               const float* __restrict__ gb,
                               float* __restrict__ out) {
    __shared__ float sh[H1];
    int t = threadIdx.x;
#pragma unroll
    for (int i = t; i < H1; i += 256) sh[i] = g_h1[i];
    __syncthreads();

    int row  = blockIdx.x * 8 + (t >> 5);
    int lane = t & 31;
    if (row >= N_NODES) return;

    const float4* w = reinterpret_cast<const float4*>(W2 + (size_t)row * H1);
    const float4* h = reinterpret_cast<const float4*>(sh);
    float s = 0.f;
#pragma unroll
    for (int i = lane; i < H1 / 4; i += 32) {  // 8 float4 per lane
        float4 wv = __ldcs(&w[i]);             // streaming: read-once weights
        float4 hv = h[i];
        s += wv.x * hv.x + wv.y * hv.y + wv.z * hv.z + wv.w * hv.w;
    }
    s = warp_sum(s);
    if (lane == 0) {
        float x  = fmaxf(s + b2[row], 0.f);
        float di = rsqrtf(g_deg[row]);
        float xd = __ldg(gw) * x * di;
        g_dinv[row] = di;
        g_xd[row]   = xd;
        out[row]    = __ldg(gb) + xd * di;
    }
}

// ---------------------------------------------------------------------------
// L4: edge scatter, 4 edges/thread with int4 index loads.
//   out[dst] += g_xd[src] * g_dinv[dst]
// ---------------------------------------------------------------------------
__global__ void k4_scatter(const int* __restrict__ src,
                           const int* __restrict__ dst,
                           float* __restrict__ out) {
    int e4 = blockIdx.x * blockDim.x + threadIdx.x;
    if (e4 * 4 >= N_EDGES) return;
    int4 s4 = reinterpret_cast<const int4*>(src)[e4];
    int4 d4 = reinterpret_cast<const int4*>(dst)[e4];
    atomicAdd(&out[d4.x], g_xd[s4.x] * g_dinv[d4.x]);
    atomicAdd(&out[d4.y], g_xd[s4.y] * g_dinv[d4.y]);
    atomicAdd(&out[d4.z], g_xd[s4.z] * g_dinv[d4.z]);
    atomicAdd(&out[d4.w], g_xd[s4.w] * g_dinv[d4.w]);
}

// ---------------------------------------------------------------------------
extern "C" void kernel_launch(void* const* d_in, const int* in_sizes, int n_in,
                              void* d_out, int out_size) {
    const float* emb = (const float*)d_in[0];
    const int*   ei  = (const int*)d_in[1];  // [2, E] int32 (JAX x64 off)
    const float* W0  = (const float*)d_in[2];
    const float* b0  = (const float*)d_in[3];
    const float* W1  = (const float*)d_in[4];
    const float* b1  = (const float*)d_in[5];
    const float* W2  = (const float*)d_in[6];
    const float* b2  = (const float*)d_in[7];
    const float* gw  = (const float*)d_in[8];
    const float* gb  = (const float*)d_in[9];
    float*       out = (float*)d_out;

    const int* src = ei;            // row 0
    const int* dst = ei + N_EDGES;  // row 1

    const int EDGE4_BLOCKS = (N_EDGES / 4 + 255) / 256;  // 1563

    k1_fc0_deginit<<<(N_NODES + 255) / 256, 256>>>(emb, W0, b0);
    k2_fc1_degcount<<<EDGE4_BLOCKS, 256>>>(W1, b1, dst);
    k3_fc2_selfmsg<<<(N_NODES + 7) / 8, 256>>>(W2, b2, gw, gb, out);
    k4_scatter<<<EDGE4_BLOCKS, 256>>>(src, dst, out);
}

// round 5
// speedup vs baseline: 1.1486x; 1.0163x over previous
#include <cuda_runtime.h>

#define N_NODES 100000
#define N_EDGES 1600000
#define H0 256
#define H1 1024
#define IN_DIM 64

// Scratch (no allocations allowed)
__device__ float g_h0[H0];
__device__ float g_h1[H1];
__device__ float g_deg[N_NODES];   // degree (incl. self loop)
__device__ float g_dinv[N_NODES];  // deg^-1/2
__device__ float g_xd[N_NODES];    // gcn_w * x[i] * dinv[i]

__device__ __forceinline__ float warp_sum(float s) {
#pragma unroll
    for (int o = 16; o; o >>= 1) s += __shfl_xor_sync(0xffffffffu, s, o);
    return s;
}

// ---------------------------------------------------------------------------
// L1: block 0 computes FC0 (64 -> 256); ALL blocks init deg slice to 1.0
// ---------------------------------------------------------------------------
__global__ void k1_fc0_deginit(const float* __restrict__ emb,
                               const float* __restrict__ W0,
                               const float* __restrict__ b0) {
    int t = threadIdx.x;
    int gi = blockIdx.x * blockDim.x + t;
    if (gi < N_NODES) g_deg[gi] = 1.0f;

    if (blockIdx.x == 0) {
        __shared__ float se[IN_DIM];
        if (t < IN_DIM) se[t] = emb[t];
        __syncthreads();

        const float4* w = reinterpret_cast<const float4*>(W0 + (size_t)t * IN_DIM);
        const float4* h = reinterpret_cast<const float4*>(se);
        float s = 0.f;
#pragma unroll
        for (int i = 0; i < IN_DIM / 4; i++) {
            float4 wv = w[i];
            float4 hv = h[i];
            s += wv.x * hv.x + wv.y * hv.y + wv.z * hv.z + wv.w * hv.w;
        }
        g_h0[t] = fmaxf(s + b0[t], 0.f);
    }
}

// ---------------------------------------------------------------------------
// L2: blocks 0..127 compute FC1 (256 -> 1024, warp-per-row);
//     ALL blocks count degrees over an 8-edge/thread slice (2x int4 loads).
// ---------------------------------------------------------------------------
__global__ void k2_fc1_degcount(const float* __restrict__ W1,
                                const float* __restrict__ b1,
                                const int*   __restrict__ dst) {
    int t = threadIdx.x;

    int e8 = blockIdx.x * blockDim.x + t;  // each handles 8 edges
    int base = e8 * 2;                     // int4 index
    if (base * 4 < N_EDGES) {
        const int4* d = reinterpret_cast<const int4*>(dst);
        int4 a = d[base];
        int4 b = d[base + 1];
        atomicAdd(&g_deg[a.x], 1.0f);
        atomicAdd(&g_deg[a.y], 1.0f);
        atomicAdd(&g_deg[a.z], 1.0f);
        atomicAdd(&g_deg[a.w], 1.0f);
        atomicAdd(&g_deg[b.x], 1.0f);
        atomicAdd(&g_deg[b.y], 1.0f);
        atomicAdd(&g_deg[b.z], 1.0f);
        atomicAdd(&g_deg[b.w], 1.0f);
    }

    if (blockIdx.x < H1 / 8) {
        __shared__ float sh[H0];
        sh[t] = g_h0[t];  // blockDim == 256 == H0
        __syncthreads();

        int row  = blockIdx.x * 8 + (t >> 5);
        int lane = t & 31;
        const float4* w = reinterpret_cast<const float4*>(W1 + (size_t)row * H0);
        const float4* h = reinterpret_cast<const float4*>(sh);
        float s = 0.f;
#pragma unroll
        for (int i = lane; i < H0 / 4; i += 32) {
            float4 wv = w[i];
            float4 hv = h[i];
            s += wv.x * hv.x + wv.y * hv.y + wv.z * hv.z + wv.w * hv.w;
        }
        s = warp_sum(s);
        if (lane == 0) g_h1[row] = fmaxf(s + b1[row], 0.f);
    }
}

// ---------------------------------------------------------------------------
// L3 (dominant): FC2 GEMV [1024]->[100000] + ReLU + fused node epilogue.
//   x        = relu(W2[row].h1 + b2[row])
//   dinv     = rsqrt(deg[row]);  xd = gcn_w * x * dinv
//   out[row] = xd[row]           (self-loop term, accumulator init)
// dinv[dst] factors out of the edge sum -> applied in k5.
// ---------------------------------------------------------------------------
__global__ void k3_fc2(const float* __restrict__ W2,
                       const float* __restrict__ b2,
                       const float* __restrict__ gw,
                       float* __restrict__ out) {
    __shared__ float sh[H1];
    int t = threadIdx.x;
#pragma unroll
    for (int i = t; i < H1; i += 256) sh[i] = g_h1[i];
    __syncthreads();

    int row  = blockIdx.x * 8 + (t >> 5);
    int lane = t & 31;
    if (row >= N_NODES) return;

    const float4* w = reinterpret_cast<const float4*>(W2 + (size_t)row * H1);
    const float4* h = reinterpret_cast<const float4*>(sh);
    float s = 0.f;
#pragma unroll
    for (int i = lane; i < H1 / 4; i += 32) {  // 8 float4 per lane
        float4 wv = __ldcs(&w[i]);             // streaming: read-once weights
        float4 hv = h[i];
        s += wv.x * hv.x + wv.y * hv.y + wv.z * hv.z + wv.w * hv.w;
    }
    s = warp_sum(s);
    if (lane == 0) {
        float x  = fmaxf(s + b2[row], 0.f);
        float di = rsqrtf(g_deg[row]);
        float xd = __ldg(gw) * x * di;
        g_dinv[row] = di;
        g_xd[row]   = xd;
        out[row]    = xd;  // self-loop contribution (pre-normalization)
    }
}

// ---------------------------------------------------------------------------
// L4: edge scatter, 8 edges/thread. ONE gather + one atomic per edge:
//   out[dst] += g_xd[src]
// ---------------------------------------------------------------------------
__global__ void k4_scatter(const int* __restrict__ src,
                           const int* __restrict__ dst,
                           float* __restrict__ out) {
    int e8 = blockIdx.x * blockDim.x + threadIdx.x;
    int base = e8 * 2;  // int4 index
    if (base * 4 >= N_EDGES) return;
    const int4* sp = reinterpret_cast<const int4*>(src);
    const int4* dp = reinterpret_cast<const int4*>(dst);
    int4 s0 = sp[base], s1 = sp[base + 1];
    int4 d0 = dp[base], d1 = dp[base + 1];

    // 8 independent gathers issue before the atomics consume them
    float v0 = __ldg(&g_xd[s0.x]);
    float v1 = __ldg(&g_xd[s0.y]);
    float v2 = __ldg(&g_xd[s0.z]);
    float v3 = __ldg(&g_xd[s0.w]);
    float v4 = __ldg(&g_xd[s1.x]);
    float v5 = __ldg(&g_xd[s1.y]);
    float v6 = __ldg(&g_xd[s1.z]);
    float v7 = __ldg(&g_xd[s1.w]);

    atomicAdd(&out[d0.x], v0);
    atomicAdd(&out[d0.y], v1);
    atomicAdd(&out[d0.z], v2);
    atomicAdd(&out[d0.w], v3);
    atomicAdd(&out[d1.x], v4);
    atomicAdd(&out[d1.y], v5);
    atomicAdd(&out[d1.z], v6);
    atomicAdd(&out[d1.w], v7);
}

// ---------------------------------------------------------------------------
// L5: final normalization  out[i] = gcn_b + dinv[i] * out[i]
// ---------------------------------------------------------------------------
__global__ void k5_finalize(float* __restrict__ out,
                            const float* __restrict__ gb) {
    int i = blockIdx.x * blockDim.x + threadIdx.x;
    if (i < N_NODES) out[i] = __ldg(gb) + g_dinv[i] * out[i];
}

// ---------------------------------------------------------------------------
extern "C" void kernel_launch(void* const* d_in, const int* in_sizes, int n_in,
                              void* d_out, int out_size) {
    const float* emb = (const float*)d_in[0];
    const int*   ei  = (const int*)d_in[1];  // [2, E] int32 (JAX x64 off)
    const float* W0  = (const float*)d_in[2];
    const float* b0  = (const float*)d_in[3];
    const float* W1  = (const float*)d_in[4];
    const float* b1  = (const float*)d_in[5];
    const float* W2  = (const float*)d_in[6];
    const float* b2  = (const float*)d_in[7];
    const float* gw  = (const float*)d_in[8];
    const float* gb  = (const float*)d_in[9];
    float*       out = (float*)d_out;

    const int* src = ei;            // row 0
    const int* dst = ei + N_EDGES;  // row 1

    const int EDGE8_BLOCKS = (N_EDGES / 8 + 255) / 256;  // 782

    k1_fc0_deginit<<<(N_NODES + 255) / 256, 256>>>(emb, W0, b0);
    k2_fc1_degcount<<<EDGE8_BLOCKS, 256>>>(W1, b1, dst);
    k3_fc2<<<(N_NODES + 7) / 8, 256>>>(W2, b2, gw, out);
    k4_scatter<<<EDGE8_BLOCKS, 256>>>(src, dst, out);
    k5_finalize<<<(N_NODES + 255) / 256, 256>>>(out, gb);
}

// round 6
// speedup vs baseline: 1.2544x; 1.0922x over previous
#include <cuda_runtime.h>

#define N_NODES 100000
#define N_EDGES 1600000
#define H0 256
#define H1 1024
#define IN_DIM 64

// Scratch (no allocations allowed)
__device__ float g_h0[H0];
__device__ float g_h1[H1];
__device__ float g_x[N_NODES];     // raw relu(FC2) output
__device__ float g_deg[N_NODES];   // degree (incl. self loop)
__device__ float g_dinv[N_NODES];  // deg^-1/2
__device__ float g_xd[N_NODES];    // gcn_w * x[i] * dinv[i]

__device__ __forceinline__ float warp_sum(float s) {
#pragma unroll
    for (int o = 16; o; o >>= 1) s += __shfl_xor_sync(0xffffffffu, s, o);
    return s;
}

// ---------------------------------------------------------------------------
// L1: block 0 computes FC0 (64 -> 256); ALL blocks init deg slice to 1.0
// ---------------------------------------------------------------------------
__global__ void k1_fc0_deginit(const float* __restrict__ emb,
                               const float* __restrict__ W0,
                               const float* __restrict__ b0) {
    int t = threadIdx.x;
    int gi = blockIdx.x * blockDim.x + t;
    if (gi < N_NODES) g_deg[gi] = 1.0f;

    if (blockIdx.x == 0) {
        __shared__ float se[IN_DIM];
        if (t < IN_DIM) se[t] = emb[t];
        __syncthreads();

        const float4* w = reinterpret_cast<const float4*>(W0 + (size_t)t * IN_DIM);
        const float4* h = reinterpret_cast<const float4*>(se);
        float s = 0.f;
#pragma unroll
        for (int i = 0; i < IN_DIM / 4; i++) {
            float4 wv = w[i];
            float4 hv = h[i];
            s += wv.x * hv.x + wv.y * hv.y + wv.z * hv.z + wv.w * hv.w;
        }
        g_h0[t] = fmaxf(s + b0[t], 0.f);
    }
}

// ---------------------------------------------------------------------------
// L2: FC1 only (256 -> 1024, warp-per-row). 128 blocks x 256 threads.
// ---------------------------------------------------------------------------
__global__ void k2_fc1(const float* __restrict__ W1,
                       const float* __restrict__ b1) {
    __shared__ float sh[H0];
    int t = threadIdx.x;
    sh[t] = g_h0[t];  // blockDim == 256 == H0
    __syncthreads();

    int row  = blockIdx.x * 8 + (t >> 5);
    int lane = t & 31;
    const float4* w = reinterpret_cast<const float4*>(W1 + (size_t)row * H0);
    const float4* h = reinterpret_cast<const float4*>(sh);
    float s = 0.f;
#pragma unroll
    for (int i = lane; i < H0 / 4; i += 32) {
        float4 wv = w[i];
        float4 hv = h[i];
        s += wv.x * hv.x + wv.y * hv.y + wv.z * hv.z + wv.w * hv.w;
    }
    s = warp_sum(s);
    if (lane == 0) g_h1[row] = fmaxf(s + b1[row], 0.f);
}

// ---------------------------------------------------------------------------
// L3 (dominant): FC2 GEMV [1024]->[100000] + ReLU, PLUS a fused degree-count
// slice (128 edges/block). The degcount atomics are fire-and-forget REDs that
// ride in the memory shadow of the 409.6 MB W2 stream; nothing in this kernel
// reads g_deg, so there is no race. grid = 12500 blocks (12500*128 = 1.6M).
// ---------------------------------------------------------------------------
__global__ void k3_fc2_degcount(const float* __restrict__ W2,
                                const float* __restrict__ b2,
                                const int*   __restrict__ dst) {
    int t = threadIdx.x;

    // degree-count slice: threads 0..127 handle one edge each (coalesced)
    if (t < 128) {
        int e = blockIdx.x * 128 + t;  // e < 12500*128 == N_EDGES
        atomicAdd(&g_deg[dst[e]], 1.0f);
    }

    __shared__ float sh[H1];
#pragma unroll
    for (int i = t; i < H1; i += 256) sh[i] = g_h1[i];
    __syncthreads();

    int row  = blockIdx.x * 8 + (t >> 5);
    int lane = t & 31;
    if (row >= N_NODES) return;

    const float4* w = reinterpret_cast<const float4*>(W2 + (size_t)row * H1);
    const float4* h = reinterpret_cast<const float4*>(sh);
    float s = 0.f;
#pragma unroll
    for (int i = lane; i < H1 / 4; i += 32) {  // 8 float4 per lane
        float4 wv = __ldcs(&w[i]);             // streaming: read-once weights
        float4 hv = h[i];
        s += wv.x * hv.x + wv.y * hv.y + wv.z * hv.z + wv.w * hv.w;
    }
    s = warp_sum(s);
    if (lane == 0) g_x[row] = fmaxf(s + b2[row], 0.f);
}

// ---------------------------------------------------------------------------
// L3b: node epilogue (deg complete after k3 kernel boundary):
//   dinv = rsqrt(deg); xd = gcn_w * x * dinv; out = xd (self-loop term)
// ---------------------------------------------------------------------------
__global__ void k3b_nodeprep(const float* __restrict__ gw,
                             float* __restrict__ out) {
    int i = blockIdx.x * blockDim.x + threadIdx.x;
    if (i >= N_NODES) return;
    float di = rsqrtf(g_deg[i]);
    float xd = __ldg(gw) * g_x[i] * di;
    g_dinv[i] = di;
    g_xd[i]   = xd;
    out[i]    = xd;  // self-loop contribution (pre-normalization)
}

// ---------------------------------------------------------------------------
// L4: edge scatter, 8 edges/thread. ONE gather + one atomic per edge:
//   out[dst] += g_xd[src]   (dst indices L2-warm from k3)
// ---------------------------------------------------------------------------
__global__ void k4_scatter(const int* __restrict__ src,
                           const int* __restrict__ dst,
                           float* __restrict__ out) {
    int e8 = blockIdx.x * blockDim.x + threadIdx.x;
    int base = e8 * 2;  // int4 index
    if (base * 4 >= N_EDGES) return;
    const int4* sp = reinterpret_cast<const int4*>(src);
    const int4* dp = reinterpret_cast<const int4*>(dst);
    int4 s0 = sp[base], s1 = sp[base + 1];
    int4 d0 = dp[base], d1 = dp[base + 1];

    float v0 = __ldg(&g_xd[s0.x]);
    float v1 = __ldg(&g_xd[s0.y]);
    float v2 = __ldg(&g_xd[s0.z]);
    float v3 = __ldg(&g_xd[s0.w]);
    float v4 = __ldg(&g_xd[s1.x]);
    float v5 = __ldg(&g_xd[s1.y]);
    float v6 = __ldg(&g_xd[s1.z]);
    float v7 = __ldg(&g_xd[s1.w]);

    atomicAdd(&out[d0.x], v0);
    atomicAdd(&out[d0.y], v1);
    atomicAdd(&out[d0.z], v2);
    atomicAdd(&out[d0.w], v3);
    atomicAdd(&out[d1.x], v4);
    atomicAdd(&out[d1.y], v5);
    atomicAdd(&out[d1.z], v6);
    atomicAdd(&out[d1.w], v7);
}

// ---------------------------------------------------------------------------
// L5: final normalization  out[i] = gcn_b + dinv[i] * out[i]
// ---------------------------------------------------------------------------
__global__ void k5_finalize(float* __restrict__ out,
                            const float* __restrict__ gb) {
    int i = blockIdx.x * blockDim.x + threadIdx.x;
    if (i < N_NODES) out[i] = __ldg(gb) + g_dinv[i] * out[i];
}

// ---------------------------------------------------------------------------
extern "C" void kernel_launch(void* const* d_in, const int* in_sizes, int n_in,
                              void* d_out, int out_size) {
    const float* emb = (const float*)d_in[0];
    const int*   ei  = (const int*)d_in[1];  // [2, E] int32 (JAX x64 off)
    const float* W0  = (const float*)d_in[2];
    const float* b0  = (const float*)d_in[3];
    const float* W1  = (const float*)d_in[4];
    const float* b1  = (const float*)d_in[5];
    const float* W2  = (const float*)d_in[6];
    const float* b2  = (const float*)d_in[7];
    const float* gw  = (const float*)d_in[8];
    const float* gb  = (const float*)d_in[9];
    float*       out = (float*)d_out;

    const int* src = ei;            // row 0
    const int* dst = ei + N_EDGES;  // row 1

    const int NODE_BLOCKS  = (N_NODES + 255) / 256;      // 391
    const int EDGE8_BLOCKS = (N_EDGES / 8 + 255) / 256;  // 782

    k1_fc0_deginit<<<NODE_BLOCKS, 256>>>(emb, W0, b0);
    k2_fc1<<<H1 / 8, 256>>>(W1, b1);
    k3_fc2_degcount<<<(N_NODES + 7) / 8, 256>>>(W2, b2, dst);
    k3b_nodeprep<<<NODE_BLOCKS, 256>>>(gw, out);
    k4_scatter<<<EDGE8_BLOCKS, 256>>>(src, dst, out);
    k5_finalize<<<NODE_BLOCKS, 256>>>(out, gb);
}